// round 1
// baseline (speedup 1.0000x reference)
#include <cuda_runtime.h>
#include <cuda_bf16.h>
#include <cstdint>

// Problem shape (fixed by the dataset):
//   image_output: [8, 512, 512, 32] f32
//   slic_output : [8, 512, 512, 1]  i32 in [0, 256]  (seg = slic-1, -1 dropped)
//   n_segments  : 256
//   output      : [256, 8, 32] f32  = per-segment mean (count of NONZERO image
//                 entries per channel as denominator)

#define BATCH 8
#define HW (512 * 512)
#define CH 32
#define NSEG 256

#define WARPS_PER_BLOCK 2
#define BLOCKS_PER_BATCH 55        // 8*55 = 440 blocks = one wave at 3 blocks/SM
#define GRID_ACC (BATCH * BLOCKS_PER_BATCH)
#define CHUNK ((HW + BLOCKS_PER_BATCH - 1) / BLOCKS_PER_BATCH)  // 4767

#define ACC_SUM_FLOATS (NSEG * CH)           // 8192
#define ACC_FLOATS (ACC_SUM_FLOATS + NSEG)   // 8448 (sums + per-seg count)
#define SMEM_BYTES (WARPS_PER_BLOCK * ACC_FLOATS * 4)  // 67584

// Scratch (device globals; no allocation allowed).
__device__ float g_part[GRID_ACC][ACC_FLOATS];   // per-block partials (~15 MB)
__device__ float g_zc[BATCH][NSEG][CH];          // count of exact-zero entries

// ---------------------------------------------------------------------------
// Kernel 1: zero the zero-correction array (g_part is fully overwritten).
// ---------------------------------------------------------------------------
__global__ void zero_kernel() {
    int i = blockIdx.x * blockDim.x + threadIdx.x;   // 65536 threads
    ((float*)g_zc)[i] = 0.0f;
}

// ---------------------------------------------------------------------------
// Kernel 2: warp-private segmented accumulation.
//   Each warp: 16 lanes x float2 channels, 2 pixels per step.
//   Private smem accumulator => NO hot-path atomics.
// ---------------------------------------------------------------------------
__global__ void __launch_bounds__(WARPS_PER_BLOCK * 32, 3)
accum_kernel(const float* __restrict__ img, const int* __restrict__ slic) {
    extern __shared__ float smem[];
    const int warp = threadIdx.x >> 5;
    const int lane = threadIdx.x & 31;
    const int h    = lane >> 4;      // which pixel of the pair
    const int sub  = lane & 15;      // channel pair index (channels 2*sub, 2*sub+1)

    float* acc = smem + warp * ACC_FLOATS;     // [NSEG][CH] sums
    float* cnt = acc + ACC_SUM_FLOATS;         // [NSEG] pixel counts

    // Zero this warp's private accumulator (float4-wide).
    float4* a4 = (float4*)acc;
    #pragma unroll
    for (int i = lane; i < ACC_FLOATS / 4; i += 32)
        a4[i] = make_float4(0.f, 0.f, 0.f, 0.f);
    __syncwarp();

    const int batch = blockIdx.x / BLOCKS_PER_BATCH;
    const int blk   = blockIdx.x % BLOCKS_PER_BATCH;
    const float* imgb  = img  + (size_t)batch * HW * CH;
    const int*   slicb = slic + (size_t)batch * HW;

    const int start = blk * CHUNK;
    int end = start + CHUNK; if (end > HW) end = HW;
    const int npairs = (end - start + 1) >> 1;

    const unsigned FULL = 0xffffffffu;
    const int U = 16;   // load batch for MLP

    for (int gbase = warp * U; gbase < npairs; gbase += WARPS_PER_BLOCK * U) {
        float2 v[U];
        int    sg[U];
        // Phase 1: issue all global loads (deep MLP, coalesced 256B per pair).
        #pragma unroll
        for (int u = 0; u < U; ++u) {
            int i = gbase + u;
            int pix = start + 2 * i + h;
            bool valid = (i < npairs) && (pix < end);
            if (valid) {
                v[u]  = *(const float2*)(imgb + (size_t)pix * CH + sub * 2);
                sg[u] = slicb[pix] - 1;
            } else {
                v[u] = make_float2(0.f, 0.f);
                sg[u] = -1;
            }
        }
        // Phase 2: smem accumulate with exact same-segment pair merging.
        #pragma unroll
        for (int u = 0; u < U; ++u) {
            int   s  = sg[u];
            int   so = __shfl_xor_sync(FULL, s, 16);
            float ox = __shfl_xor_sync(FULL, v[u].x, 16);
            float oy = __shfl_xor_sync(FULL, v[u].y, 16);
            bool dup = (s == so);    // both halves hit the same segment
            if (s >= 0) {
                // Rare exact zeros: correct the per-channel count globally.
                if (v[u].x == 0.0f) atomicAdd(&g_zc[batch][s][sub * 2], 1.0f);
                if (v[u].y == 0.0f) atomicAdd(&g_zc[batch][s][sub * 2 + 1], 1.0f);
                if (!dup || h == 0) {
                    float ax = v[u].x + (dup ? ox : 0.0f);
                    float ay = v[u].y + (dup ? oy : 0.0f);
                    float2* p = (float2*)(acc + s * CH + sub * 2);
                    float2 cur = *p;          // LDS.64, conflict-free
                    cur.x += ax;
                    cur.y += ay;
                    *p = cur;                 // STS.64
                    if (sub == 0) cnt[s] += (dup ? 2.0f : 1.0f);
                }
            }
        }
    }

    // Merge the two warps' accumulators and stream the partial to global.
    __syncthreads();
    const float4* p0 = (const float4*)(smem);
    const float4* p1 = (const float4*)(smem + ACC_FLOATS);
    float4* outp = (float4*)g_part[blockIdx.x];
    #pragma unroll 4
    for (int i = threadIdx.x; i < ACC_FLOATS / 4; i += WARPS_PER_BLOCK * 32) {
        float4 a = p0[i], b = p1[i];
        a.x += b.x; a.y += b.y; a.z += b.z; a.w += b.w;
        outp[i] = a;
    }
}

// ---------------------------------------------------------------------------
// Kernel 3: reduce per-block partials and divide. out[s][b][c].
// One warp handles one (b, s) across its 32 channels => coalesced sum loads,
// broadcast count loads (L2-resident, 450 KB).
// ---------------------------------------------------------------------------
__global__ void finalize_kernel(float* __restrict__ out) {
    int idx = blockIdx.x * blockDim.x + threadIdx.x;   // 65536 = B*S*C
    int c = idx & (CH - 1);
    int s = (idx >> 5) & (NSEG - 1);
    int b = idx >> 13;

    float sum = 0.0f, cn = 0.0f;
    int pb = b * BLOCKS_PER_BATCH;
    #pragma unroll 11
    for (int k = 0; k < BLOCKS_PER_BATCH; ++k) {
        sum += g_part[pb + k][s * CH + c];
        cn  += g_part[pb + k][ACC_SUM_FLOATS + s];
    }
    cn -= g_zc[b][s][c];   // per-channel nonzero count
    out[((size_t)s * BATCH + b) * CH + c] = sum / cn;
}

// ---------------------------------------------------------------------------
extern "C" void kernel_launch(void* const* d_in, const int* in_sizes, int n_in,
                              void* d_out, int out_size) {
    const float* img  = (const float*)d_in[0];
    const int*   slic = (const int*)d_in[1];
    float* out = (float*)d_out;

    zero_kernel<<<256, 256>>>();

    cudaFuncSetAttribute(accum_kernel,
                         cudaFuncAttributeMaxDynamicSharedMemorySize, SMEM_BYTES);
    accum_kernel<<<GRID_ACC, WARPS_PER_BLOCK * 32, SMEM_BYTES>>>(img, slic);

    finalize_kernel<<<256, 256>>>(out);
}

// round 2
// speedup vs baseline: 1.9095x; 1.9095x over previous
#include <cuda_runtime.h>
#include <cuda_bf16.h>
#include <cstdint>

// image_output: [8, 512, 512, 32] f32; slic: [8,512,512,1] i32 in [0,256]
// out[s][b][c] = sum(img where slic-1==s) / count(nonzero img where slic-1==s)

#define BATCH 8
#define HW (512 * 512)
#define CH 32
#define NSEG 256
#define ROWS (NSEG + 1)            // +1 dummy row for invalid/OOB pixels

#define WARPS_PER_BLOCK 2
#define BLOCKS_PER_BATCH 55        // 440 blocks = one wave at 3 blocks/SM
#define GRID_ACC (BATCH * BLOCKS_PER_BATCH)
#define CHUNK ((HW + BLOCKS_PER_BATCH - 1) / BLOCKS_PER_BATCH)  // 4767

#define ACCF (ROWS * CH)                     // 8224 floats per warp (dummy last)
#define SMEM_BYTES (WARPS_PER_BLOCK * ACCF * 4)   // 65792

#define PREP_BLOCKS 256
#define PIX_PER_PREP (BATCH * HW / PREP_BLOCKS)   // 8192

__device__ float g_part[GRID_ACC][NSEG * CH];     // per-block sum partials
__device__ float g_cntp[PREP_BLOCKS][NSEG];       // per-prep-block pixel counts
__device__ float g_zc[BATCH][NSEG][CH];           // exact-zero corrections (rare)

// ---------------------------------------------------------------------------
// Kernel 1: per-segment pixel counts from slic only + zero g_zc.
// 256 blocks x 256 threads; block covers 8192 consecutive pixels (one batch
// per 32 blocks). Block-private smem counters -> per-block partial (no races).
// ---------------------------------------------------------------------------
__global__ void prep_kernel(const int* __restrict__ slic) {
    __shared__ int cnt[NSEG];
    const int t = threadIdx.x;
    cnt[t & (NSEG - 1)] = 0;                       // 256 threads cover 256 slots
    ((float*)g_zc)[blockIdx.x * 256 + t] = 0.0f;   // 256*256 = 65536 floats
    __syncthreads();

    const int base = blockIdx.x * PIX_PER_PREP;
    #pragma unroll 8
    for (int k = 0; k < PIX_PER_PREP / 256; ++k) {
        int s = slic[base + k * 256 + t] - 1;      // coalesced
        if (s >= 0) atomicAdd(&cnt[s], 1);
    }
    __syncthreads();
    g_cntp[blockIdx.x][t & (NSEG - 1)] = (float)cnt[t & (NSEG - 1)];
}

// ---------------------------------------------------------------------------
// Kernel 2: branchless warp-private segmented accumulation.
// One pixel per warp step: lane c accumulates channel c. Invalid pixels go to
// the dummy row. No shuffles, no divergence, no hot-path atomics.
// ---------------------------------------------------------------------------
__global__ void __launch_bounds__(WARPS_PER_BLOCK * 32, 3)
accum_kernel(const float* __restrict__ img, const int* __restrict__ slic) {
    extern __shared__ float smem[];
    const int warp = threadIdx.x >> 5;
    const int lane = threadIdx.x & 31;
    float* acc = smem + warp * ACCF;

    float4* a4 = (float4*)acc;                     // zero private accumulator
    #pragma unroll
    for (int i = lane; i < ACCF / 4; i += 32)
        a4[i] = make_float4(0.f, 0.f, 0.f, 0.f);
    __syncwarp();

    const int batch = blockIdx.x / BLOCKS_PER_BATCH;
    const int blk   = blockIdx.x % BLOCKS_PER_BATCH;
    const float* imgb  = img  + (size_t)batch * HW * CH;
    const int*   slicb = slic + (size_t)batch * HW;

    const int start = blk * CHUNK;
    int end = start + CHUNK; if (end > HW) end = HW;

    const unsigned FULL = 0xffffffffu;
    const int U = 32;

    for (int p0 = start + warp * U; p0 < end; p0 += WARPS_PER_BLOCK * U) {
        float v[U];
        int   row[U];
        // Phase 1: issue all loads (deep MLP; 128B coalesced per pixel).
        #pragma unroll
        for (int u = 0; u < U; ++u) {
            int  pix = p0 + u;
            bool ok  = pix < end;
            float x = 0.0f;
            int   s = -1;
            if (ok) {
                x = __ldcs(imgb + (size_t)pix * CH + lane);
                s = slicb[pix] - 1;                // broadcast, L1-resident
            }
            v[u]   = x;
            row[u] = (s < 0) ? NSEG : s;           // NSEG = dummy row
        }
        // Phase 2: unconditional LDS -> FADD -> STS (bank = lane, conflict-free).
        bool zany = false;
        #pragma unroll
        for (int u = 0; u < U; ++u) {
            float* p = acc + row[u] * CH + lane;
            *p += v[u];
            zany |= (v[u] == 0.0f) & (row[u] != NSEG);
        }
        // Rare path: exact-zero image entries (warp-uniformly not taken).
        if (__ballot_sync(FULL, zany)) {
            #pragma unroll
            for (int u = 0; u < U; ++u)
                if (v[u] == 0.0f && row[u] != NSEG)
                    atomicAdd(&g_zc[batch][row[u]][lane], 1.0f);
        }
    }

    // Merge the two warps and stream the partial (real 256 rows only).
    __syncthreads();
    const float4* p0w = (const float4*)(smem);
    const float4* p1w = (const float4*)(smem + ACCF);
    float4* outp = (float4*)g_part[blockIdx.x];
    #pragma unroll 4
    for (int i = threadIdx.x; i < NSEG * CH / 4; i += WARPS_PER_BLOCK * 32) {
        float4 a = p0w[i], b = p1w[i];
        a.x += b.x; a.y += b.y; a.z += b.z; a.w += b.w;
        outp[i] = a;
    }
}

// ---------------------------------------------------------------------------
// Kernel 3: reduce partials, form denominator, divide. out[s][b][c].
// ---------------------------------------------------------------------------
__global__ void finalize_kernel(float* __restrict__ out) {
    int idx = blockIdx.x * blockDim.x + threadIdx.x;   // 65536 = B*S*C
    int c = idx & (CH - 1);
    int s = (idx >> 5) & (NSEG - 1);
    int b = idx >> 13;

    float sum = 0.0f;
    int pb = b * BLOCKS_PER_BATCH;
    #pragma unroll 11
    for (int k = 0; k < BLOCKS_PER_BATCH; ++k)
        sum += g_part[pb + k][s * CH + c];             // coalesced over c

    float cn = 0.0f;
    int cb = b * (PREP_BLOCKS / BATCH);
    #pragma unroll 8
    for (int k = 0; k < PREP_BLOCKS / BATCH; ++k)
        cn += g_cntp[cb + k][s];                       // warp-broadcast

    cn -= g_zc[b][s][c];
    out[((size_t)s * BATCH + b) * CH + c] = sum / cn;
}

// ---------------------------------------------------------------------------
extern "C" void kernel_launch(void* const* d_in, const int* in_sizes, int n_in,
                              void* d_out, int out_size) {
    const float* img  = (const float*)d_in[0];
    const int*   slic = (const int*)d_in[1];
    float* out = (float*)d_out;

    prep_kernel<<<PREP_BLOCKS, 256>>>(slic);

    cudaFuncSetAttribute(accum_kernel,
                         cudaFuncAttributeMaxDynamicSharedMemorySize, SMEM_BYTES);
    accum_kernel<<<GRID_ACC, WARPS_PER_BLOCK * 32, SMEM_BYTES>>>(img, slic);

    finalize_kernel<<<256, 256>>>(out);
}

// round 3
// speedup vs baseline: 3.3582x; 1.7586x over previous
#include <cuda_runtime.h>
#include <cuda_bf16.h>
#include <cstdint>

// image_output: [8, 512, 512, 32] f32; slic: [8,512,512,1] i32 in [0,256]
// out[s][b][c] = sum(img where slic-1==s) / count(nonzero img where slic-1==s)

#define BATCH 8
#define HW (512 * 512)
#define CH 32
#define NSEG 256
#define ROWS (NSEG + 1)            // +1 dummy row for slic==0 pixels

#define WARPS_PER_BLOCK 2
#define BPB 55                     // blocks per batch; 440 = one wave @3/SM
#define GRID_ACC (BATCH * BPB)
#define CHUNK ((HW + BPB - 1) / BPB)   // 4767

#define ACCF (ROWS * CH)           // 8224 floats per warp accumulator
#define SMEM_BYTES (WARPS_PER_BLOCK * ACCF * 4)   // 65792 per block

#define PREP_BLOCKS 512
#define PIX_PER_PREP (BATCH * HW / PREP_BLOCKS)   // 4096
#define CNT_BLK_PER_BATCH (PREP_BLOCKS / BATCH)   // 64

__device__ float g_part[GRID_ACC][NSEG * CH];     // per-block sum partials
__device__ float g_cntp[PREP_BLOCKS][NSEG];       // per-prep-block pixel counts
__device__ float g_zc[BATCH][NSEG][CH];           // exact-zero corrections (rare)

// ---------------------------------------------------------------------------
// Kernel 1: per-segment pixel counts (slic only, int4-vectorized) + zero g_zc.
// ---------------------------------------------------------------------------
__global__ void prep_kernel(const int* __restrict__ slic) {
    __shared__ int cnt[NSEG];
    const int t = threadIdx.x;
    cnt[t] = 0;
    int zidx = blockIdx.x * 256 + t;               // 131072 threads cover 65536
    if (zidx < BATCH * NSEG * CH) ((float*)g_zc)[zidx] = 0.0f;
    __syncthreads();

    const int4* p = (const int4*)(slic + blockIdx.x * PIX_PER_PREP);
    #pragma unroll
    for (int k = 0; k < PIX_PER_PREP / 4 / 256; ++k) {   // 4 iterations
        int4 s4 = p[k * 256 + t];
        if (s4.x) atomicAdd(&cnt[s4.x - 1], 1);
        if (s4.y) atomicAdd(&cnt[s4.y - 1], 1);
        if (s4.z) atomicAdd(&cnt[s4.z - 1], 1);
        if (s4.w) atomicAdd(&cnt[s4.w - 1], 1);
    }
    __syncthreads();
    g_cntp[blockIdx.x][t] = (float)cnt[t];
}

// ---------------------------------------------------------------------------
// Kernel 2: warp-private segmented accumulation.
// Branch-free main loop; depth-2 software-pipelined smem RMW with exact
// same-row repair; slic fetched once per 32 pixels and shuffled.
// ---------------------------------------------------------------------------
__global__ void __launch_bounds__(WARPS_PER_BLOCK * 32, 3)
accum_kernel(const float* __restrict__ img, const int* __restrict__ slic) {
    extern __shared__ float smem[];
    const int warp = threadIdx.x >> 5;
    const int lane = threadIdx.x & 31;
    float* acc = smem + warp * ACCF;

    float4* a4 = (float4*)acc;
    for (int i = lane; i < ACCF / 4; i += 32)
        a4[i] = make_float4(0.f, 0.f, 0.f, 0.f);
    __syncwarp();

    const int batch = blockIdx.x / BPB;
    const int blk   = blockIdx.x % BPB;
    const float* imgb  = img  + (size_t)batch * HW * CH;
    const int*   slicb = slic + (size_t)batch * HW;

    const int start = blk * CHUNK;
    int end = start + CHUNK; if (end > HW) end = HW;
    const int n = end - start;
    const int nround = n >> 6;                  // full 64-pixel rounds

    const unsigned FULL = 0xffffffffu;
    const int U = 32;

    for (int r = 0; r < nround; ++r) {
        const int p0 = start + (r << 6) + (warp << 5);

        // ---- Phase 1: coalesced loads, no predicates ----
        const int sv = slicb[p0 + lane];        // one LDG covers 32 pixels
        const float* ib = imgb + (size_t)p0 * CH + lane;
        float v[U];
        #pragma unroll
        for (int u = 0; u < U; ++u)
            v[u] = __ldcs(ib + u * CH);         // LDG.32, imm offsets, deep MLP
        int row[U];
        #pragma unroll
        for (int u = 0; u < U; ++u) {
            int s = __shfl_sync(FULL, sv, u);
            row[u] = (s == 0) ? NSEG : (s - 1); // NSEG = dummy row
        }

        // ---- Phase 2: depth-2 pipelined RMW with exact repair ----
        float pend0 = acc[row[0] * CH + lane];
        float pend1 = acc[row[1] * CH + lane];
        int   lr = -1, l2r = -1;
        float lv = 0.f, l2v = 0.f;
        bool  zany = false;
        #pragma unroll
        for (int u = 0; u < U; ++u) {
            float a = pend0;
            a = (row[u] == l2r) ? l2v : a;      // repair vs store at u-2
            a = (row[u] == lr)  ? lv  : a;      // repair vs store at u-1 (newer)
            zany |= (v[u] == 0.0f) & (row[u] != NSEG);
            a += v[u];
            float np = 0.f;
            if (u + 2 < U)                      // compile-time (unrolled)
                np = acc[row[u + 2] * CH + lane];  // prefetch BEFORE the store
            acc[row[u] * CH + lane] = a;
            l2r = lr;  l2v = lv;
            lr  = row[u]; lv = a;
            pend0 = pend1; pend1 = np;
        }

        // Rare path: exact-zero image entries (warp-uniformly not taken).
        if (__ballot_sync(FULL, zany)) {
            #pragma unroll
            for (int u = 0; u < U; ++u)
                if (v[u] == 0.0f && row[u] != NSEG)
                    atomicAdd(&g_zc[batch][row[u]][lane], 1.0f);
        }
    }

    // ---- Tail: < 64 pixels, simple path ----
    for (int p = start + (nround << 6) + warp; p < end; p += WARPS_PER_BLOCK) {
        int s = slicb[p];
        int rw = (s == 0) ? NSEG : (s - 1);
        float x = imgb[(size_t)p * CH + lane];
        acc[rw * CH + lane] += x;
        if (x == 0.0f && rw != NSEG)
            atomicAdd(&g_zc[batch][rw][lane], 1.0f);
    }

    // Merge the two warps' accumulators; stream real 256 rows to global.
    __syncthreads();
    const float4* p0w = (const float4*)(smem);
    const float4* p1w = (const float4*)(smem + ACCF);
    float4* outp = (float4*)g_part[blockIdx.x];
    #pragma unroll 4
    for (int i = threadIdx.x; i < NSEG * CH / 4; i += WARPS_PER_BLOCK * 32) {
        float4 a = p0w[i], b = p1w[i];
        a.x += b.x; a.y += b.y; a.z += b.z; a.w += b.w;
        outp[i] = a;
    }
}

// ---------------------------------------------------------------------------
// Kernel 3: reduce partials, form denominator, divide. out[s][b][c].
// ---------------------------------------------------------------------------
__global__ void finalize_kernel(float* __restrict__ out) {
    int idx = blockIdx.x * blockDim.x + threadIdx.x;   // 65536 = B*S*C
    int c = idx & (CH - 1);
    int s = (idx >> 5) & (NSEG - 1);
    int b = idx >> 13;

    float sum = 0.0f;
    int pb = b * BPB;
    #pragma unroll 11
    for (int k = 0; k < BPB; ++k)
        sum += g_part[pb + k][s * CH + c];             // coalesced over c

    float cn = 0.0f;
    int cb = b * CNT_BLK_PER_BATCH;
    #pragma unroll 16
    for (int k = 0; k < CNT_BLK_PER_BATCH; ++k)
        cn += g_cntp[cb + k][s];                       // warp-broadcast

    cn -= g_zc[b][s][c];
    out[((size_t)s * BATCH + b) * CH + c] = sum / cn;
}

// ---------------------------------------------------------------------------
extern "C" void kernel_launch(void* const* d_in, const int* in_sizes, int n_in,
                              void* d_out, int out_size) {
    const float* img  = (const float*)d_in[0];
    const int*   slic = (const int*)d_in[1];
    float* out = (float*)d_out;

    prep_kernel<<<PREP_BLOCKS, 256>>>(slic);

    cudaFuncSetAttribute(accum_kernel,
                         cudaFuncAttributeMaxDynamicSharedMemorySize, SMEM_BYTES);
    accum_kernel<<<GRID_ACC, WARPS_PER_BLOCK * 32, SMEM_BYTES>>>(img, slic);

    finalize_kernel<<<256, 256>>>(out);
}